// round 11
// baseline (speedup 1.0000x reference)
#include <cuda_runtime.h>
#include <cstdint>

// ---------------------------------------------------------------------------
// Quan_adder2d, single fused kernel, 224 self-sufficient work blocks.
// out[n,f,ho,wo] = -sum_{c,i,j} | qw[f,c,i,j] - qx[n,c,ho+i-1,wo+j-1] |
// Integer min-trick on the global 16-bit x grid:
//   sum|.| = s * (W_SUM[f] + X_SUM[win] - 2*sum min(w_int, x_int))
// Each block: own x-minmax slice (atomic) -> own W-half quant (u8, no x dep)
// -> raw x stage -> spin for global minmax -> quantize/regrid -> hot loop.
// ---------------------------------------------------------------------------

#define N_BATCH 4
#define C_IN    64
#define HW      28
#define F_OUT   64
#define KDIM    576
#define QX_MAX  65535.0f
#define QW_MAX  255.0f

#define WB      224
#define THREADS 448
#define SLICES  8
#define CPP     4
#define TPS     56              // 8 fgrp x 7 wog

__device__ unsigned g_min_u = 0xFFFFFFFFu;
__device__ unsigned g_max_u = 0u;
__device__ unsigned g_cnt   = 0;
__device__ unsigned g_fin   = 0;

__device__ __forceinline__ unsigned enc_f(float f) {
    int i = __float_as_int(f);
    return (i < 0) ? ~(unsigned)i : ((unsigned)i | 0x80000000u);
}
__device__ __forceinline__ float dec_f(unsigned u) {
    int i = (u & 0x80000000u) ? (int)(u & 0x7FFFFFFFu) : (int)(~u);
    return __int_as_float(i);
}
__device__ __forceinline__ unsigned minu2(unsigned a, unsigned b) {
    unsigned r;
    asm("min.u16x2 %0, %1, %2;" : "=r"(r) : "r"(a), "r"(b));
    return r;
}
#define DPB 0x00000101u   // dp2a byte pair (1,1): sums both u16 halves

// smem (u32 units):
//   SWI  [288 k'][32 f'] packed w pairs            0..9216
//   SXI  [32 cp][3][32] packed x pairs          9216..12288
//   UN   union(SXR raw x 5760 | RED 3584 + RPART 240 + RS 30 + WPART 128)
//                                              12288..18048
//   WQ8  [32 f'][580B pitch] u8 quantized W    18048..22688
#define SWI_OFF   0
#define SXI_OFF   9216
#define UN_OFF    12288
#define RED_OFF   12288
#define RPART_OFF 15872
#define RS_OFF    16112
#define WPART_OFF 16144     // [4][32]
#define WQ8_OFF   18048     // pitch 145 u32 per f'
#define SMEM_U32  22688
#define SMEM_BYTES (SMEM_U32 * 4)   // 90752

__global__ void __launch_bounds__(THREADS, 2)
k_fused(const float* __restrict__ x, const float* __restrict__ W,
        float* __restrict__ out) {
    const int tid = threadIdx.x;
    const int wb  = blockIdx.x;
    const int ho  = wb % 28;
    const int nz  = wb / 28;
    const int n   = nz & 3;
    const int fh  = nz >> 2;

    extern __shared__ unsigned smem[];
    unsigned* swi   = smem + SWI_OFF;
    unsigned* sxi   = smem + SXI_OFF;
    float*    sxr   = (float*)(smem + UN_OFF);
    uint4*    red   = (uint4*)(smem + RED_OFF);
    unsigned* rpart = smem + RPART_OFF;
    unsigned* rs    = smem + RS_OFF;
    unsigned* wpart = smem + WPART_OFF;
    unsigned* wq8u  = smem + WQ8_OFF;
    unsigned char* wq8b = (unsigned char*)wq8u;

    __shared__ float smn[14], smx[14];
    __shared__ float wsc[32], wzp[32];

    const int warp = tid >> 5;
    const int lane = tid & 31;

    // ---- phase A: this block's x min/max slice (224 float4, 1 per thread) ----
    {
        float mn = 1e30f, mx = -1e30f;
        if (tid < 224) {
            float4 v = ((const float4*)x)[wb * 224 + tid];
            mn = fminf(fminf(v.x, v.y), fminf(v.z, v.w));
            mx = fmaxf(fmaxf(v.x, v.y), fmaxf(v.z, v.w));
        }
        #pragma unroll
        for (int o = 16; o > 0; o >>= 1) {
            mn = fminf(mn, __shfl_xor_sync(0xffffffffu, mn, o));
            mx = fmaxf(mx, __shfl_xor_sync(0xffffffffu, mx, o));
        }
        if (lane == 0) { smn[warp] = mn; smx[warp] = mx; }
        __syncthreads();
        if (tid < 32) {
            mn = (tid < 7) ? smn[tid] : 1e30f;   // only warps 0..6 held data
            mx = (tid < 7) ? smx[tid] : -1e30f;
            #pragma unroll
            for (int o = 16; o > 0; o >>= 1) {
                mn = fminf(mn, __shfl_xor_sync(0xffffffffu, mn, o));
                mx = fmaxf(mx, __shfl_xor_sync(0xffffffffu, mx, o));
            }
            if (tid == 0) {
                atomicMin(&g_min_u, enc_f(mn));
                atomicMax(&g_max_u, enc_f(mx));
                __threadfence();
                atomicAdd(&g_cnt, 1u);
            }
        }
    }

    // ---- phase B: W-half per-f quant to u8 (no x dependency) ----
    for (int fl = warp; fl < 32; fl += 14) {
        const float* wf = W + (fh * 32 + fl) * KDIM;
        float v[18];
        float mn = 1e30f, mx = -1e30f;
        #pragma unroll
        for (int t = 0; t < 18; ++t) {
            v[t] = wf[lane + t * 32];
            mn = fminf(mn, v[t]);
            mx = fmaxf(mx, v[t]);
        }
        #pragma unroll
        for (int o = 16; o > 0; o >>= 1) {
            mn = fminf(mn, __shfl_xor_sync(0xffffffffu, mn, o));
            mx = fmaxf(mx, __shfl_xor_sync(0xffffffffu, mx, o));
        }
        float scale = fmaxf(__fdiv_rn(mx - mn, QW_MAX), 1e-12f);
        float zp    = rintf(__fdiv_rn(-mn, scale));
        #pragma unroll
        for (int t = 0; t < 18; ++t) {
            float q = fminf(fmaxf(rintf(__fdiv_rn(v[t], scale)) + zp, 0.0f),
                            QW_MAX);
            wq8b[fl * 580 + lane + t * 32] = (unsigned char)q;
        }
        if (lane == 0) { wsc[fl] = scale; wzp[fl] = zp; }
    }

    // ---- phase C: raw x window staging ----
    for (int idx = tid; idx < 5760; idx += THREADS) {
        int c   = idx / 90;
        int rem = idx - c * 90;
        int i   = rem / 30;
        int col = rem - i * 30;
        int h   = ho + i - 1;
        int w   = col - 1;
        float v = 0.0f;
        if ((unsigned)h < (unsigned)HW && (unsigned)w < (unsigned)HW)
            v = x[((n * C_IN + c) * HW + h) * HW + w];
        sxr[idx] = v;
    }

    // ---- phase D: wait for global minmax ----
    __syncthreads();
    if (tid == 0) {
        while (atomicAdd(&g_cnt, 0u) < (unsigned)WB) __nanosleep(32);
    }
    __syncthreads();

    const float xmn  = dec_f(g_min_u);
    const float xmx  = dec_f(g_max_u);
    const float s    = fmaxf(__fdiv_rn(xmx - xmn, QX_MAX), 1e-12f);
    const float xzp  = rintf(__fdiv_rn(-xmn, s));
    const float invs = __fdiv_rn(1.0f, s);

    // ---- phase E: quantize + pack x (quant(0) == zp handles padding) ----
    for (int idx = tid; idx < 2880; idx += THREADS) {
        int c   = idx / 90;
        int rem = idx - c * 90;
        int i   = rem / 30;
        int col = rem - i * 30;
        float a  = sxr[c * 90 + i * 30 + col];
        float bb = sxr[(c + 32) * 90 + i * 30 + col];
        unsigned vlo = (unsigned)fminf(fmaxf(rintf(__fdiv_rn(a, s)) + xzp, 0.0f),
                                       QX_MAX);
        unsigned vhi = (unsigned)fminf(fmaxf(rintf(__fdiv_rn(bb, s)) + xzp, 0.0f),
                                       QX_MAX);
        sxi[c * 96 + i * 32 + col] = vlo | (vhi << 16);
    }
    __syncthreads();   // sxr dead after this

    // ---- phase F: regrid W u8 -> packed u16x2 swi[k'][f'] ----
    // k4 in [0,72): u32 of 4 low-channel bytes (k'=4*k4..+3), paired with +288B.
    {
        const int fl = tid & 31;
        const int kg = tid >> 5;            // 0..13, 6 k4-values each
        const float zpw = wzp[fl];
        const float scw = wsc[fl];
        int k40 = kg * 6;
        int k4e = k40 + 6; if (k4e > 72) k4e = 72;
        for (int k4 = k40; k4 < k4e; ++k4) {
            unsigned a = wq8u[fl * 145 + k4];        // bytes k' = 4k4..4k4+3
            unsigned b = wq8u[fl * 145 + 72 + k4];   // bytes k' + 288
            #pragma unroll
            for (int d = 0; d < 4; ++d) {
                float w0 = ((float)((a >> (8 * d)) & 255u) - zpw) * scw;
                float w1 = ((float)((b >> (8 * d)) & 255u) - zpw) * scw;
                unsigned q0 = (unsigned)fminf(fmaxf(rintf(w0 * invs) + xzp, 0.0f),
                                              65535.0f);
                unsigned q1 = (unsigned)fminf(fmaxf(rintf(w1 * invs) + xzp, 0.0f),
                                              65535.0f);
                swi[(4 * k4 + d) * 32 + fl] = q0 | (q1 << 16);
            }
        }
    }
    __syncthreads();

    // ---- phase G: correction partials (read after next barrier) ----
    if (tid < 240) {              // X window column sums: col = tid/8, p = tid&7
        int col = tid >> 3;
        int p   = tid & 7;
        unsigned ssum = 0;
        #pragma unroll
        for (int cc = 0; cc < 4; ++cc)
            #pragma unroll
            for (int i = 0; i < 3; ++i)
                ssum = __dp2a_lo(sxi[(p * 4 + cc) * 96 + i * 32 + col], DPB, ssum);
        rpart[col * 8 + p] = ssum;
    } else if (tid >= 256 && tid < 384) {   // W sums: p = 0..3, fl = tid&31
        int p  = (tid - 256) >> 5;
        int fl = tid & 31;
        unsigned ssum = 0;
        for (int k = p * 72; k < p * 72 + 72; ++k)
            ssum = __dp2a_lo(swi[k * 32 + fl], DPB, ssum);
        wpart[p * 32 + fl] = ssum;
    }

    // ---- hot loop ----
    const int slice = tid / TPS;
    const int t     = tid - slice * TPS;
    const int fgrp  = t & 7;
    const int wog   = t >> 3;
    const int f0    = fgrp * 4;
    const int wo0   = wog * 4;
    const int cp0   = slice * CPP;

    unsigned acc[4][4];
    #pragma unroll
    for (int a = 0; a < 4; ++a)
        #pragma unroll
        for (int b2 = 0; b2 < 4; ++b2) acc[a][b2] = 0u;

    const unsigned* xrow = sxi + cp0 * 96;
    const unsigned* wrow = swi + cp0 * 9 * 32 + f0;

    #pragma unroll
    for (int cp = 0; cp < CPP; ++cp) {
        #pragma unroll
        for (int i = 0; i < 3; ++i) {
            uint4 wp0 = *(const uint4*)(wrow + (i * 3 + 0) * 32);
            uint4 wp1 = *(const uint4*)(wrow + (i * 3 + 1) * 32);
            uint4 wp2 = *(const uint4*)(wrow + (i * 3 + 2) * 32);
            const unsigned* xr = xrow + i * 32 + wo0;
            uint4 xa = *(const uint4*)xr;
            uint2 xb = *(const uint2*)(xr + 4);
            unsigned xsv[6] = { xa.x, xa.y, xa.z, xa.w, xb.x, xb.y };
            #pragma unroll
            for (int k = 0; k < 4; ++k) {
                unsigned x0 = xsv[k], x1 = xsv[k + 1], x2 = xsv[k + 2];
                acc[0][k] = __dp2a_lo(minu2(wp0.x, x0), DPB, acc[0][k]);
                acc[1][k] = __dp2a_lo(minu2(wp0.y, x0), DPB, acc[1][k]);
                acc[2][k] = __dp2a_lo(minu2(wp0.z, x0), DPB, acc[2][k]);
                acc[3][k] = __dp2a_lo(minu2(wp0.w, x0), DPB, acc[3][k]);
                acc[0][k] = __dp2a_lo(minu2(wp1.x, x1), DPB, acc[0][k]);
                acc[1][k] = __dp2a_lo(minu2(wp1.y, x1), DPB, acc[1][k]);
                acc[2][k] = __dp2a_lo(minu2(wp1.z, x1), DPB, acc[2][k]);
                acc[3][k] = __dp2a_lo(minu2(wp1.w, x1), DPB, acc[3][k]);
                acc[0][k] = __dp2a_lo(minu2(wp2.x, x2), DPB, acc[0][k]);
                acc[1][k] = __dp2a_lo(minu2(wp2.y, x2), DPB, acc[1][k]);
                acc[2][k] = __dp2a_lo(minu2(wp2.z, x2), DPB, acc[2][k]);
                acc[3][k] = __dp2a_lo(minu2(wp2.w, x2), DPB, acc[3][k]);
            }
        }
        xrow += 96;
        wrow += 9 * 32;
    }

    uint4 va[4];
    #pragma unroll
    for (int fl = 0; fl < 4; ++fl)
        va[fl] = make_uint4(acc[fl][0], acc[fl][1], acc[fl][2], acc[fl][3]);

#define RSLOT(sl, fl) red[(((sl) * TPS + t) << 2) + (fl)]
#define RADD(sl)                                                  \
    { _Pragma("unroll") for (int fl = 0; fl < 4; ++fl) {          \
        uint4 o = RSLOT(sl, fl);                                  \
        va[fl].x += o.x; va[fl].y += o.y;                         \
        va[fl].z += o.z; va[fl].w += o.w; } }
#define RSTORE(sl)                                                \
    { _Pragma("unroll") for (int fl = 0; fl < 4; ++fl) RSLOT(sl, fl) = va[fl]; }

    // 8 -> 4 -> 2 -> 1 (rs finalized in parallel)
    if (slice >= 4) RSTORE(slice - 4);
    __syncthreads();
    if (tid < 30) {
        unsigned ssum = 0;
        #pragma unroll
        for (int p = 0; p < 8; ++p) ssum += rpart[tid * 8 + p];
        rs[tid] = ssum;
    }
    if (slice < 4) RADD(slice);
    __syncthreads();
    if (slice == 2 || slice == 3) RSTORE(slice - 2);
    __syncthreads();
    if (slice < 2) RADD(slice);
    __syncthreads();
    if (slice == 1) RSTORE(0);
    __syncthreads();
    if (slice == 0) {
        RADD(0);
        int xsum[4];
        #pragma unroll
        for (int k = 0; k < 4; ++k)
            xsum[k] = (int)(rs[wo0 + k] + rs[wo0 + k + 1] + rs[wo0 + k + 2]);
        const int fbase = fh * 32 + f0;
        float* op = out + ((n * F_OUT + fbase) * HW + ho) * HW + wo0;
        #pragma unroll
        for (int fl = 0; fl < 4; ++fl) {
            int ws = (int)(wpart[f0 + fl] + wpart[32 + f0 + fl] +
                           wpart[64 + f0 + fl] + wpart[96 + f0 + fl]);
            float4 o;
            o.x = s * (float)(2 * (int)va[fl].x - ws - xsum[0]);
            o.y = s * (float)(2 * (int)va[fl].y - ws - xsum[1]);
            o.z = s * (float)(2 * (int)va[fl].z - ws - xsum[2]);
            o.w = s * (float)(2 * (int)va[fl].w - ws - xsum[3]);
            *(float4*)(op + fl * HW * HW) = o;
        }
    }
#undef RSLOT
#undef RADD
#undef RSTORE

    // completion ticket: last block resets globals for the next launch
    __syncthreads();
    if (tid == 0) {
        unsigned v = atomicAdd(&g_fin, 1u);
        if (v == (unsigned)(WB - 1)) {
            g_min_u = 0xFFFFFFFFu;
            g_max_u = 0u;
            g_cnt   = 0u;
            g_fin   = 0u;
            __threadfence();
        }
    }
}

extern "C" void kernel_launch(void* const* d_in, const int* in_sizes, int n_in,
                              void* d_out, int out_size) {
    const float* x = (const float*)d_in[0];
    const float* W = (const float*)d_in[1];
    float* out = (float*)d_out;

    cudaFuncSetAttribute(k_fused, cudaFuncAttributeMaxDynamicSharedMemorySize,
                         SMEM_BYTES);
    k_fused<<<WB, THREADS, SMEM_BYTES>>>(x, W, out);
}

// round 13
// speedup vs baseline: 1.3439x; 1.3439x over previous
#include <cuda_runtime.h>
#include <cstdint>

// ---------------------------------------------------------------------------
// Quan_adder2d. Two kernels:
//  k_prep: blocks 0,1 -> W quant/regrid/pack + wsum (spin on minmax)
//          blocks 2..33 -> x minmax partials
//          blocks 34..131 -> x quantize+pack to g_qxi (spin on minmax)
//  k_main: grid (28 ho, 4 n, 2 fhalf), 448 thr, 2 blocks/SM; hot loop =
//          min.u16x2 + dp2a (min-trick: sum|.| = s*(WSUM + XSUM - 2*sum min)).
// ---------------------------------------------------------------------------

#define N_BATCH 4
#define C_IN    64
#define HW      28
#define F_OUT   64
#define KDIM    576
#define QX_MAX  65535.0f
#define QW_MAX  255.0f

#define MMB     32
#define XPB     98
#define PREPG   (2 + MMB + XPB)   // 132
#define SLICES  8
#define CPP     4
#define TPS     56                // 8 fgrp x 7 wog
#define THREADS (SLICES*TPS)      // 448

__device__ float    g_bmin[MMB];
__device__ float    g_bmax[MMB];
__device__ unsigned g_cnt = 0;
__device__ float    g_sprm[2];             // xscale, xzp
__device__ unsigned g_wsum[F_OUT];
__device__ unsigned g_swi[2 * 288 * 32];   // [fhalf][k'][f'] packed u16x2
__device__ unsigned g_qxi[N_BATCH * 32 * HW * HW];  // [n][cpair][h][w]

__device__ __forceinline__ unsigned minu2(unsigned a, unsigned b) {
    unsigned r;
    asm("min.u16x2 %0, %1, %2;" : "=r"(r) : "r"(a), "r"(b));
    return r;
}
#define DPB 0x00000101u   // dp2a byte pair (1,1): sums both u16 halves

// ---------------------------------------------------------------------------
#define PREP_SMEM (32 * 289 * 4)   // 36992 B (W path packed staging, pitch 289)

__global__ void __launch_bounds__(1024, 1) k_prep(const float* __restrict__ W,
                                                  const float* __restrict__ x) {
    extern __shared__ unsigned sp[];   // W blocks: [32 f][pitch 289] packed
    const int tid = threadIdx.x;

    // ---------------- x min/max partial blocks ----------------
    if (blockIdx.x >= 2 && blockIdx.x < 2 + MMB) {
        const float4* x4 = (const float4*)x;
        const int n4  = (N_BATCH * C_IN * HW * HW) / 4;
        int bid = blockIdx.x - 2;
        float mn = 1e30f, mx = -1e30f;
        for (int i = bid * 1024 + tid; i < n4; i += MMB * 1024) {
            float4 v = x4[i];
            mn = fminf(fminf(fminf(mn, v.x), v.y), fminf(v.z, v.w));
            mx = fmaxf(fmaxf(fmaxf(mx, v.x), v.y), fmaxf(v.z, v.w));
        }
        #pragma unroll
        for (int o = 16; o > 0; o >>= 1) {
            mn = fminf(mn, __shfl_xor_sync(0xffffffffu, mn, o));
            mx = fmaxf(mx, __shfl_xor_sync(0xffffffffu, mx, o));
        }
        __shared__ float smn[32], smx[32];
        int warp = tid >> 5, lane = tid & 31;
        if (lane == 0) { smn[warp] = mn; smx[warp] = mx; }
        __syncthreads();
        if (warp == 0) {
            mn = smn[lane];
            mx = smx[lane];
            #pragma unroll
            for (int o = 16; o > 0; o >>= 1) {
                mn = fminf(mn, __shfl_xor_sync(0xffffffffu, mn, o));
                mx = fmaxf(mx, __shfl_xor_sync(0xffffffffu, mx, o));
            }
            if (lane == 0) {
                g_bmin[bid] = mn;
                g_bmax[bid] = mx;
                __threadfence();
                atomicAdd(&g_cnt, 1u);
            }
        }
        return;
    }

    // ---------------- x quantize+pack blocks ----------------
    if (blockIdx.x >= 2 + MMB) {
        const int ib = (blockIdx.x - 2 - MMB) * 1024 + tid;  // 0..100351
        __shared__ float prm[2];
        if (tid == 0) {
            while (atomicAdd(&g_cnt, 0u) < (unsigned)MMB) __nanosleep(64);
            float xmn = 1e30f, xmx = -1e30f;
            #pragma unroll 8
            for (int i = 0; i < MMB; ++i) {
                xmn = fminf(xmn, g_bmin[i]);
                xmx = fmaxf(xmx, g_bmax[i]);
            }
            float s = fmaxf(__fdiv_rn(xmx - xmn, QX_MAX), 1e-12f);
            prm[0] = s;
            prm[1] = rintf(__fdiv_rn(-xmn, s));
        }
        __syncthreads();
        const float s  = prm[0];
        const float zp = prm[1];
        int hw  = ib % 784;
        int cpn = ib / 784;          // 0..127
        int cp  = cpn & 31;
        int n   = cpn >> 5;
        float a = x[(n * 64 + cp) * 784 + hw];
        float b = x[(n * 64 + cp + 32) * 784 + hw];
        unsigned vlo = (unsigned)fminf(fmaxf(rintf(__fdiv_rn(a, s)) + zp, 0.0f),
                                       QX_MAX);
        unsigned vhi = (unsigned)fminf(fmaxf(rintf(__fdiv_rn(b, s)) + zp, 0.0f),
                                       QX_MAX);
        g_qxi[ib] = vlo | (vhi << 16);
        return;
    }

    // ---------------- W blocks (0,1): quant + regrid + pack + wsum ----------
    const int b    = blockIdx.x;
    const int warp = tid >> 5;
    const int lane = tid & 31;
    const int f    = b * 32 + warp;

    const float* wf = W + f * KDIM;
    float v[18];
    float mn = 1e30f, mx = -1e30f;
    #pragma unroll
    for (int t = 0; t < 18; ++t) {       // k = lane + t*32
        v[t] = wf[lane + t * 32];
        mn = fminf(mn, v[t]);
        mx = fmaxf(mx, v[t]);
    }
    #pragma unroll
    for (int o = 16; o > 0; o >>= 1) {
        mn = fminf(mn, __shfl_xor_sync(0xffffffffu, mn, o));
        mx = fmaxf(mx, __shfl_xor_sync(0xffffffffu, mx, o));
    }
    float scale = fmaxf(__fdiv_rn(mx - mn, QW_MAX), 1e-12f);
    float zp    = rintf(__fdiv_rn(-mn, scale));
    #pragma unroll
    for (int t = 0; t < 18; ++t) {       // dequantized weight (float)
        float q = fminf(fmaxf(rintf(__fdiv_rn(v[t], scale)) + zp, 0.0f), QW_MAX);
        v[t] = (q - zp) * scale;
    }

    __shared__ float xs_s[2];
    if (tid == 0) {
        while (atomicAdd(&g_cnt, 0u) < (unsigned)MMB) __nanosleep(64);
        float xmn = 1e30f, xmx = -1e30f;
        #pragma unroll 8
        for (int i = 0; i < MMB; ++i) {
            xmn = fminf(xmn, g_bmin[i]);
            xmx = fmaxf(xmx, g_bmax[i]);
        }
        float xs = fmaxf(__fdiv_rn(xmx - xmn, QX_MAX), 1e-12f);
        xs_s[0] = xs;
        xs_s[1] = rintf(__fdiv_rn(-xmn, xs));
        if (b == 0) { g_sprm[0] = xs_s[0]; g_sprm[1] = xs_s[1]; }
    }
    __syncthreads();
    const float xs   = xs_s[0];
    const float xzp  = xs_s[1];
    const float invs = __fdiv_rn(1.0f, xs);

    unsigned wq[18];
    #pragma unroll
    for (int t = 0; t < 18; ++t)
        wq[t] = (unsigned)fminf(fmaxf(rintf(v[t] * invs) + xzp, 0.0f), 65535.0f);
    unsigned ssum = 0;
    #pragma unroll
    for (int t = 0; t < 9; ++t) {        // pair: k'=lane+t*32 with k'+288
        unsigned p = wq[t] | (wq[t + 9] << 16);
        sp[warp * 289 + lane + t * 32] = p;
        ssum = __dp2a_lo(p, DPB, ssum);
    }
    #pragma unroll
    for (int o = 16; o > 0; o >>= 1)
        ssum += __shfl_xor_sync(0xffffffffu, ssum, o);
    if (lane == 0) g_wsum[f] = ssum;
    __syncthreads();

    // transposed coalesced store, pitch 289
    const int j  = tid & 31;
    const int kk = tid >> 5;
    #pragma unroll
    for (int p = 0; p < 9; ++p) {
        int k2 = p * 32 + kk;
        g_swi[b * 9216 + k2 * 32 + j] = sp[j * 289 + k2];
    }
}

// ---------------------------------------------------------------------------
// k_main: grid (28 ho, 4 n, 2 fhalf), 448 threads, 2 blocks/SM
// ---------------------------------------------------------------------------
#define SWI_OFF   0                    // [288][32] packed w
#define SXI_OFF   9216                 // [32 cp][3][32] packed x
#define RED_OFF   12288                // 1568 uint4 = 6272 u32
#define RPART_OFF 18560                // [30][8]
#define RS_OFF    18800                // [30]
#define SMEM_U32  18832
#define SMEM_BYTES (SMEM_U32 * 4)      // 75328

__global__ void __launch_bounds__(THREADS, 2) k_main(float* __restrict__ out) {
    const int ho  = blockIdx.x;
    const int n   = blockIdx.y;
    const int fh  = blockIdx.z;
    const int tid = threadIdx.x;

    // reset prep counter for the next launch (stream-ordered after k_prep)
    if (tid == 0 && ho == 0 && n == 0 && fh == 0) g_cnt = 0u;

    extern __shared__ unsigned smem[];
    unsigned* swi   = smem + SWI_OFF;
    unsigned* sxi   = smem + SXI_OFF;
    uint4*    red   = (uint4*)(smem + RED_OFF);
    unsigned* rpart = smem + RPART_OFF;
    unsigned* rs    = smem + RS_OFF;

    const float    s   = g_sprm[0];
    const unsigned zpu = (unsigned)g_sprm[1];
    const unsigned zpp = zpu | (zpu << 16);

    // stage packed W half (straight copy, L2 resident)
    {
        const uint4* gsrc = (const uint4*)(g_swi + fh * 9216);
        uint4*       sdst = (uint4*)swi;
        for (int i = tid; i < 2304; i += THREADS) sdst[i] = gsrc[i];
    }

    // stage packed x window (pure copy with bounds; padding -> zp pair)
    for (int idx = tid; idx < 2880; idx += THREADS) {
        int c   = idx / 90;
        int rem = idx - c * 90;
        int i   = rem / 30;
        int col = rem - i * 30;
        int h   = ho + i - 1;
        int w   = col - 1;
        unsigned v = zpp;
        if ((unsigned)h < (unsigned)HW && (unsigned)w < (unsigned)HW)
            v = g_qxi[((n * 32 + c) * HW + h) * HW + w];
        sxi[c * 96 + i * 32 + col] = v;
    }
    __syncthreads();

    // X window column-sum partials (X_SUM correction)
    if (tid < 240) {
        int col = tid >> 3;
        int p   = tid & 7;
        unsigned ssum = 0;
        #pragma unroll
        for (int cc = 0; cc < 4; ++cc)
            #pragma unroll
            for (int i = 0; i < 3; ++i)
                ssum = __dp2a_lo(sxi[(p * 4 + cc) * 96 + i * 32 + col], DPB, ssum);
        rpart[col * 8 + p] = ssum;
    }

    // ---- hot loop ----
    const int slice = tid / TPS;
    const int t     = tid - slice * TPS;
    const int fgrp  = t & 7;
    const int wog   = t >> 3;
    const int f0    = fgrp * 4;
    const int wo0   = wog * 4;
    const int cp0   = slice * CPP;

    unsigned acc[4][4];
    #pragma unroll
    for (int a = 0; a < 4; ++a)
        #pragma unroll
        for (int b2 = 0; b2 < 4; ++b2) acc[a][b2] = 0u;

    const unsigned* xrow = sxi + cp0 * 96;
    const unsigned* wrow = swi + cp0 * 9 * 32 + f0;

    #pragma unroll
    for (int cp = 0; cp < CPP; ++cp) {
        #pragma unroll
        for (int i = 0; i < 3; ++i) {
            uint4 wp0 = *(const uint4*)(wrow + (i * 3 + 0) * 32);
            uint4 wp1 = *(const uint4*)(wrow + (i * 3 + 1) * 32);
            uint4 wp2 = *(const uint4*)(wrow + (i * 3 + 2) * 32);
            const unsigned* xr = xrow + i * 32 + wo0;
            uint4 xa = *(const uint4*)xr;
            uint2 xb = *(const uint2*)(xr + 4);
            unsigned xsv[6] = { xa.x, xa.y, xa.z, xa.w, xb.x, xb.y };
            #pragma unroll
            for (int k = 0; k < 4; ++k) {
                unsigned x0 = xsv[k], x1 = xsv[k + 1], x2 = xsv[k + 2];
                acc[0][k] = __dp2a_lo(minu2(wp0.x, x0), DPB, acc[0][k]);
                acc[1][k] = __dp2a_lo(minu2(wp0.y, x0), DPB, acc[1][k]);
                acc[2][k] = __dp2a_lo(minu2(wp0.z, x0), DPB, acc[2][k]);
                acc[3][k] = __dp2a_lo(minu2(wp0.w, x0), DPB, acc[3][k]);
                acc[0][k] = __dp2a_lo(minu2(wp1.x, x1), DPB, acc[0][k]);
                acc[1][k] = __dp2a_lo(minu2(wp1.y, x1), DPB, acc[1][k]);
                acc[2][k] = __dp2a_lo(minu2(wp1.z, x1), DPB, acc[2][k]);
                acc[3][k] = __dp2a_lo(minu2(wp1.w, x1), DPB, acc[3][k]);
                acc[0][k] = __dp2a_lo(minu2(wp2.x, x2), DPB, acc[0][k]);
                acc[1][k] = __dp2a_lo(minu2(wp2.y, x2), DPB, acc[1][k]);
                acc[2][k] = __dp2a_lo(minu2(wp2.z, x2), DPB, acc[2][k]);
                acc[3][k] = __dp2a_lo(minu2(wp2.w, x2), DPB, acc[3][k]);
            }
        }
        xrow += 96;
        wrow += 9 * 32;
    }

    uint4 va[4];
    #pragma unroll
    for (int fl = 0; fl < 4; ++fl)
        va[fl] = make_uint4(acc[fl][0], acc[fl][1], acc[fl][2], acc[fl][3]);

    // flat reduction: slices 1..7 store; slice 0 sums all
    if (slice > 0) {
        #pragma unroll
        for (int fl = 0; fl < 4; ++fl)
            red[(((slice - 1) * TPS + t) << 2) + fl] = va[fl];
    }
    __syncthreads();
    if (tid < 30) {
        unsigned ssum = 0;
        #pragma unroll
        for (int p = 0; p < 8; ++p) ssum += rpart[tid * 8 + p];
        rs[tid] = ssum;
    }
    if (slice == 0) {
        #pragma unroll
        for (int sl = 0; sl < 7; ++sl) {
            #pragma unroll
            for (int fl = 0; fl < 4; ++fl) {
                uint4 o = red[((sl * TPS + t) << 2) + fl];
                va[fl].x += o.x; va[fl].y += o.y;
                va[fl].z += o.z; va[fl].w += o.w;
            }
        }
    }
    __syncthreads();
    if (slice == 0) {
        int xsum[4];
        #pragma unroll
        for (int k = 0; k < 4; ++k)
            xsum[k] = (int)(rs[wo0 + k] + rs[wo0 + k + 1] + rs[wo0 + k + 2]);
        const int fbase = fh * 32 + f0;
        float* op = out + ((n * F_OUT + fbase) * HW + ho) * HW + wo0;
        #pragma unroll
        for (int fl = 0; fl < 4; ++fl) {
            int ws = (int)g_wsum[fbase + fl];
            float4 o;
            o.x = s * (float)(2 * (int)va[fl].x - ws - xsum[0]);
            o.y = s * (float)(2 * (int)va[fl].y - ws - xsum[1]);
            o.z = s * (float)(2 * (int)va[fl].z - ws - xsum[2]);
            o.w = s * (float)(2 * (int)va[fl].w - ws - xsum[3]);
            *(float4*)(op + fl * HW * HW) = o;
        }
    }
}

extern "C" void kernel_launch(void* const* d_in, const int* in_sizes, int n_in,
                              void* d_out, int out_size) {
    const float* x = (const float*)d_in[0];
    const float* W = (const float*)d_in[1];
    float* out = (float*)d_out;

    cudaFuncSetAttribute(k_prep, cudaFuncAttributeMaxDynamicSharedMemorySize,
                         PREP_SMEM);
    cudaFuncSetAttribute(k_main, cudaFuncAttributeMaxDynamicSharedMemorySize,
                         SMEM_BYTES);

    k_prep<<<PREPG, 1024, PREP_SMEM>>>(W, x);
    dim3 grid(HW, N_BATCH, 2);
    k_main<<<grid, THREADS, SMEM_BYTES>>>(out);
}